// round 10
// baseline (speedup 1.0000x reference)
#include <cuda_runtime.h>

#define TT 32
#define BB 256
#define C1 64
#define C2 128
#define C3 256

// ---- device scratch (allocation-free) ----
__device__ float g_s1c[BB*C1*64], g_s1v[BB*C1*64];
__device__ float g_s2c[BB*C2*36], g_s2v[BB*C2*36];
__device__ float g_pool[BB*C2*9];
__device__ float g_s3c[BB*C3], g_s3v[BB*C3];
__device__ float g_flat[TT*BB*C3];
__device__ float g_stcc[BB*C3], g_stcv[BB*C3];
__device__ float g_src[BB*C3], g_srv[BB*C3];
__device__ float g_r[2*BB*C3];
__device__ float g_sfc[BB*128], g_sfv[BB*128];
__device__ float g_w2t[576*C2];
__device__ float g_w3t[1152*C3];
__device__ float g_tcwt[3*C3*C3];
__device__ float g_recwt[C3*C3];
__device__ float g_fc1wt[C3*128];

typedef unsigned long long u64;
__device__ __forceinline__ u64 pk2(float lo, float hi){
    u64 r; asm("mov.b64 %0, {%1,%2};" : "=l"(r) : "f"(lo), "f"(hi)); return r;
}
__device__ __forceinline__ void upk2(u64 v, float &lo, float &hi){
    asm("mov.b64 {%0,%1}, %2;" : "=f"(lo), "=f"(hi) : "l"(v));
}
__device__ __forceinline__ u64 ffma2(u64 a, u64 b, u64 c){
    u64 d; asm("fma.rn.f32x2 %0, %1, %2, %3;" : "=l"(d) : "l"(a), "l"(b), "l"(c)); return d;
}
// CUBA-LIF; state = (cur, veff = vlt*(1-spike))
__device__ __forceinline__ float lifs(float z, float* cp, float* vp){
    float cur = 0.5f*(*cp) + z;
    float vlt = 0.75f*(*vp) + cur;
    bool s = vlt > 0.5f;
    *cp = cur; *vp = s ? 0.0f : vlt;
    return s ? 1.0f : 0.0f;
}

__global__ void k_zero(float* __restrict__ dout){
    int i0 = blockIdx.x*blockDim.x + threadIdx.x, st = gridDim.x*blockDim.x;
    for(int i=i0;i<BB*C1*64;i+=st){ g_s1c[i]=0.f; g_s1v[i]=0.f; }
    for(int i=i0;i<BB*C2*36;i+=st){ g_s2c[i]=0.f; g_s2v[i]=0.f; }
    for(int i=i0;i<BB*C3;i+=st){
        g_s3c[i]=0.f; g_s3v[i]=0.f; g_stcc[i]=0.f; g_stcv[i]=0.f;
        g_src[i]=0.f; g_srv[i]=0.f; g_r[i]=0.f; g_r[BB*C3+i]=0.f;
    }
    for(int i=i0;i<BB*128;i+=st){ g_sfc[i]=0.f; g_sfv[i]=0.f; }
    for(int i=i0;i<BB*2;i+=st) dout[i]=0.f;
}

__global__ void k_prep(const float* __restrict__ w2, const float* __restrict__ w3,
                       const float* __restrict__ tcw, const float* __restrict__ recw,
                       const float* __restrict__ fc1w){
    int i0 = blockIdx.x*blockDim.x + threadIdx.x, st = gridDim.x*blockDim.x;
    for(int i=i0;i<C2*576;i+=st){ int co=i/576, k=i-co*576; g_w2t[k*C2+co]=w2[i]; }
    for(int i=i0;i<C3*1152;i+=st){ int co=i/1152, k=i-co*1152; g_w3t[k*C3+co]=w3[i]; }
    for(int i=i0;i<3*C3*C3;i+=st){
        int j=i/(C3*C3), r=i-j*C3*C3, o=r/C3, k=r-o*C3;
        g_tcwt[j*C3*C3 + k*C3 + o]=tcw[i];
    }
    for(int i=i0;i<C3*C3;i+=st){ int o=i/C3, k=i-o*C3; g_recwt[k*C3+o]=recw[i]; }
    for(int i=i0;i<128*C3;i+=st){ int o=i/C3, k=i-o*C3; g_fc1wt[k*128+o]=fc1w[i]; }
}

// ===== fused conv1 + conv2 + LIF + avgpool (unchanged — verified) =====
#define K2_CH    8
#define K2_CHF   (K2_CH*9*C2)
#define K2_SMEM  (8192*8 + 2*K2_CHF*4)

__global__ __launch_bounds__(256) void k_conv12(const float* __restrict__ x,
                                                const float* __restrict__ w1,
                                                const float* __restrict__ b1,
                                                const float* __restrict__ b2, int t){
    extern __shared__ char smraw[];
    u64*   sc1 = (u64*)smraw;
    float* sw  = (float*)(smraw + 8192*8);
    __shared__ float sx[200];
    int tid = threadIdx.x, b0 = blockIdx.x*2;

    if (tid < 200){
        int im = tid/100, p = tid-100*im;
        sx[tid] = x[((b0+im)*100 + p)*TT + t];
    }
    __syncthreads();
    #pragma unroll 4
    for (int l=0; l<32; l++){
        int i = l*256 + tid;
        int im = i>>12, e = i&4095;
        int c = e>>6, pos = e&63, ii = pos>>3, jj = pos&7;
        float z = __ldg(&b1[c]);
        const float* wp = w1 + c*9;
        const float* xp = sx + im*100 + ii*10 + jj;
        #pragma unroll
        for(int ki=0;ki<3;ki++)
            #pragma unroll
            for(int kj=0;kj<3;kj++)
                z += __ldg(&wp[ki*3+kj]) * xp[ki*10+kj];
        int gidx = ((b0+im)<<12) + e;
        float v = lifs(z, &g_s1c[gidx], &g_s1v[gidx]);
        sc1[i] = pk2(v,v);
    }

    int h   = tid>>7, lt = tid&127;
    int cog = lt>>2, quad = lt&3;
    int co0 = cog*4;
    int oi0 = (quad>>1)*3, oj0 = (quad&1)*3;
    const u64* scb = sc1 + h*4096;

    float4 bb = *(const float4*)&b2[co0];
    u64 acc[2][9];
    {
        u64 p0 = pk2(bb.x,bb.y), p1 = pk2(bb.z,bb.w);
        #pragma unroll
        for(int p=0;p<9;p++){ acc[0][p]=p0; acc[1][p]=p1; }
    }

    float4 pre[9];
    {
        const float4* src = (const float4*)g_w2t + tid;
        #pragma unroll
        for(int j=0;j<9;j++) pre[j] = src[j*256];
    }
    __syncthreads();
    {
        float4* dst = (float4*)sw + tid;
        #pragma unroll
        for(int j=0;j<9;j++) dst[j*256] = pre[j];
    }
    __syncthreads();

    for (int ch=0; ch<64/K2_CH; ch++){
        if (ch < 64/K2_CH - 1){
            const float4* src = (const float4*)g_w2t + (ch+1)*(K2_CHF/4) + tid;
            #pragma unroll
            for(int j=0;j<9;j++) pre[j] = src[j*256];
        }
        const float* wbuf = sw + (ch&1)*K2_CHF;
        #pragma unroll 2
        for (int cl=0; cl<K2_CH; cl++){
            int ci = ch*K2_CH + cl;
            u64 win[25];
            const u64* wr = scb + ci*64 + oi0*8 + oj0;
            #pragma unroll
            for(int di=0;di<5;di++)
                #pragma unroll
                for(int dj=0;dj<5;dj++)
                    win[di*5+dj] = wr[di*8+dj];
            #pragma unroll
            for(int kk=0;kk<9;kk++){
                const int ki = kk/3, kj = kk - ki*3;
                float4 wv = *(const float4*)&wbuf[(cl*9+kk)*C2 + co0];
                u64 w0 = pk2(wv.x,wv.y), w1p = pk2(wv.z,wv.w);
                #pragma unroll
                for(int p=0;p<9;p++){
                    const int pi = p/3, pj = p - pi*3;
                    u64 s = win[(pi+ki)*5 + (pj+kj)];
                    acc[0][p] = ffma2(w0,  s, acc[0][p]);
                    acc[1][p] = ffma2(w1p, s, acc[1][p]);
                }
            }
        }
        if (ch < 64/K2_CH - 1){
            float4* dst = (float4*)(sw + ((ch+1)&1)*K2_CHF) + tid;
            #pragma unroll
            for(int j=0;j<9;j++) dst[j*256] = pre[j];
        }
        __syncthreads();
    }

    float* zbuf = (float*)sc1;
    #pragma unroll
    for(int cp=0;cp<2;cp++)
        #pragma unroll
        for(int p=0;p<9;p++){
            float z0,z1; upk2(acc[cp][p], z0, z1);
            int di=p/3, dj=p-di*3, pidx=(oi0+di)*6 + (oj0+dj);
            zbuf[(h*C2 + co0+2*cp  )*36 + pidx] = z0;
            zbuf[(h*C2 + co0+2*cp+1)*36 + pidx] = z1;
        }
    __syncthreads();
    float* sc2 = sw;
    for(int i=tid;i<2*C2*36;i+=256){
        int gidx = b0*C2*36 + i;
        sc2[i] = lifs(zbuf[i], &g_s2c[gidx], &g_s2v[gidx]);
    }
    __syncthreads();
    for(int i=tid;i<2*C2*9;i+=256){
        int hh = i/(C2*9), rem = i - hh*(C2*9);
        int c = rem/9, pp = rem-c*9, pi = pp/3, pj = pp-pi*3;
        const float* s2 = sc2 + (hh*C2 + c)*36;
        g_pool[b0*C2*9 + i] = 0.25f*(s2[(2*pi)*6+2*pj] + s2[(2*pi)*6+2*pj+1]
                                   + s2[(2*pi+1)*6+2*pj] + s2[(2*pi+1)*6+2*pj+1]);
    }
}

// ===== conv3: K=1152 GEMV + LIF, smem double-buffered weight staging =====
// 128 blocks = 64 img-quads x 2 co-halves. 512 threads = 128 co x 4 K-groups.
#define K3_SMEM (18432 + 32768 + 6144)   // sp_t | sw[2][4096] | red[3][512]
__global__ __launch_bounds__(512) void k_conv3(const float* __restrict__ b3, int t){
    extern __shared__ char sm3[];
    float* sp_t = (float*)sm3;                    // [1152][4]
    float* sw   = (float*)(sm3 + 18432);          // [2][4096]
    float* red  = (float*)(sm3 + 18432 + 32768);  // [3][512]
    int blk = blockIdx.x, b0 = (blk>>1)*4, ch = blk&1, tid = threadIdx.x;
    for(int i=tid;i<1152;i+=512){
        float4 v;
        v.x=g_pool[(b0+0)*1152+i]; v.y=g_pool[(b0+1)*1152+i];
        v.z=g_pool[(b0+2)*1152+i]; v.w=g_pool[(b0+3)*1152+i];
        *(float4*)&sp_t[i*4]=v;
    }
    const float4* wsrc = (const float4*)g_w3t;
    float4 pre[2];
    #pragma unroll
    for(int j=0;j<2;j++){
        int fidx = tid + j*512, kr = fidx>>5, c4 = fidx&31;
        pre[j] = wsrc[kr*64 + ch*32 + c4];
    }
    {
        float4* dst = (float4*)sw;
        #pragma unroll
        for(int j=0;j<2;j++) dst[tid + j*512] = pre[j];
    }
    __syncthreads();
    int co_l = tid&127, kh = tid>>7;
    int co = ch*128 + co_l;
    float a0=0.f,a1=0.f,a2=0.f,a3=0.f;
    for(int c=0;c<36;c++){
        if(c<35){
            #pragma unroll
            for(int j=0;j<2;j++){
                int fidx = tid + j*512, kr = fidx>>5, c4 = fidx&31;
                pre[j] = wsrc[((c+1)*32+kr)*64 + ch*32 + c4];
            }
        }
        const float* wb = sw + (c&1)*4096;
        const float* st = sp_t + c*128;
        #pragma unroll
        for(int j=0;j<8;j++){
            int kk = kh*8+j;
            float w = wb[kk*128+co_l];
            float4 sv = *(const float4*)(st + kk*4);
            a0+=w*sv.x; a1+=w*sv.y; a2+=w*sv.z; a3+=w*sv.w;
        }
        if(c<35){
            float4* dst = (float4*)(sw + ((c+1)&1)*4096);
            #pragma unroll
            for(int j=0;j<2;j++) dst[tid+j*512] = pre[j];
        }
        __syncthreads();
    }
    if(kh>0) *(float4*)&red[(kh-1)*512 + co_l*4] = make_float4(a0,a1,a2,a3);
    __syncthreads();
    if(kh==0){
        #pragma unroll
        for(int q=0;q<3;q++){
            float4 rv = *(const float4*)&red[q*512 + co_l*4];
            a0+=rv.x; a1+=rv.y; a2+=rv.z; a3+=rv.w;
        }
        float bz = b3[co];
        float av[4] = {a0+bz, a1+bz, a2+bz, a3+bz};
        #pragma unroll
        for(int img=0;img<4;img++){
            int gi = (b0+img)*C3 + co;
            g_flat[t*BB*C3 + gi] = lifs(av[img], &g_s3c[gi], &g_s3v[gi]);
        }
    }
}

// ===== fused tail: tc + LIF, rec + LIF, fc1 + LIF, fc2. Staged weights + f32x2. =====
// 64 blocks x 4 images, 256 threads.
#define TL_SW   65536
#define TL_SMEM (TL_SW + 12288 + 4096 + 4096 + 2048 + 2048)   // 90112
__global__ __launch_bounds__(256) void k_tail(const float* __restrict__ tcb,
                       const float* __restrict__ recb,
                       const float* __restrict__ fc1b, const float* __restrict__ fc2w,
                       const float* __restrict__ tsw, float* __restrict__ dout,
                       int t, int nb){
    extern __shared__ char smt[];
    float* sw   = (float*)smt;                 // [2][8192]
    float* sf_t = (float*)(smt + TL_SW);       // [3][1024]
    float* r_t  = sf_t + 3*1024;
    float* sr_t = r_t + 1024;
    float* f1_t = sr_t + 1024;
    float* red2 = f1_t + 512;
    int b0 = blockIdx.x*4, tid = threadIdx.x;
    for(int j=0;j<nb;j++){
        const float* fl = g_flat + (t-(nb-1)+j)*BB*C3 + b0*C3;
        float4 v; v.x=fl[tid]; v.y=fl[C3+tid]; v.z=fl[2*C3+tid]; v.w=fl[3*C3+tid];
        *(float4*)&sf_t[j*1024 + tid*4] = v;
    }
    {
        const float* rp = g_r + ((t+1)&1)*BB*C3 + b0*C3;
        float4 v; v.x=rp[tid]; v.y=rp[C3+tid]; v.z=rp[2*C3+tid]; v.w=rp[3*C3+tid];
        *(float4*)&r_t[tid*4] = v;
    }
    int NC = nb*8 + 8;
    auto wbase = [&](int i)->const float4*{
        if(i < nb*8) return (const float4*)(g_tcwt + (i>>3)*C3*C3 + (i&7)*32*C3);
        return (const float4*)(g_recwt + (i-nb*8)*32*C3);
    };
    float4 pre[8];
    {
        const float4* s = wbase(0);
        #pragma unroll
        for(int j=0;j<8;j++) pre[j] = s[tid + j*256];
    }
    {
        float4* d = (float4*)sw;
        #pragma unroll
        for(int j=0;j<8;j++) d[tid + j*256] = pre[j];
    }
    __syncthreads();
    int co = tid;
    u64 a01, a23;
    {
        float bs = 0.f;
        for(int j=0;j<nb;j++) bs += tcb[j*C3+co];
        a01 = pk2(bs,bs); a23 = a01;
    }
    for(int i=0;i<NC;i++){
        if(i+1<NC){
            const float4* s = wbase(i+1);
            #pragma unroll
            for(int j=0;j<8;j++) pre[j] = s[tid + j*256];
        }
        if(i == nb*8){
            float x0,x1,x2,x3; upk2(a01,x0,x1); upk2(a23,x2,x3);
            float av[4] = {x0,x1,x2,x3};
            float rb = recb[co];
            float tcs[4];
            #pragma unroll
            for(int img=0;img<4;img++){
                int gi = (b0+img)*C3 + co;
                tcs[img] = lifs(av[img], &g_stcc[gi], &g_stcv[gi]);
            }
            a01 = pk2(tcs[0]+rb, tcs[1]+rb);
            a23 = pk2(tcs[2]+rb, tcs[3]+rb);
        }
        const float* wb = sw + (i&1)*8192;
        const float* st = (i < nb*8) ? (sf_t + (i>>3)*1024 + (i&7)*128)
                                     : (r_t + (i-nb*8)*128);
        #pragma unroll
        for(int kk=0;kk<32;kk++){
            float w = wb[kk*256+co];
            u64 wd = pk2(w,w);
            const u64* sp2 = (const u64*)(st + kk*4);
            a01 = ffma2(wd, sp2[0], a01);
            a23 = ffma2(wd, sp2[1], a23);
        }
        if(i+1<NC){
            float4* d = (float4*)(sw + ((i+1)&1)*8192);
            #pragma unroll
            for(int j=0;j<8;j++) d[tid + j*256] = pre[j];
        }
        __syncthreads();
    }
    {
        float x0,x1,x2,x3; upk2(a01,x0,x1); upk2(a23,x2,x3);
        float av[4] = {x0,x1,x2,x3};
        float rs[4];
        #pragma unroll
        for(int img=0;img<4;img++){
            int gi = (b0+img)*C3 + co;
            rs[img] = lifs(av[img], &g_src[gi], &g_srv[gi]);
            g_r[(t&1)*BB*C3 + gi] = rs[img];
        }
        *(float4*)&sr_t[co*4] = make_float4(rs[0],rs[1],rs[2],rs[3]);
    }
    __syncthreads();
    // ---- fc1: 8 chunks of 32 K-rows x 128 co (K=256 total) ----
    int o = tid&127, kh = tid>>7;
    u64 f01 = pk2(0.f,0.f), f23 = f01;
    const float4* fsrc = (const float4*)g_fc1wt;
    float4 fpre[4];
    #pragma unroll
    for(int j=0;j<4;j++) fpre[j] = fsrc[tid + j*256];
    {
        float4* d = (float4*)sw;
        #pragma unroll
        for(int j=0;j<4;j++) d[tid + j*256] = fpre[j];
    }
    __syncthreads();
    for(int c=0;c<8;c++){
        if(c<7){
            #pragma unroll
            for(int j=0;j<4;j++) fpre[j] = fsrc[(c+1)*1024 + tid + j*256];
        }
        const float* wb = sw + (c&1)*8192;
        const float* st = sr_t + c*128;
        #pragma unroll
        for(int j=0;j<16;j++){
            int kk = kh*16+j;
            float w = wb[kk*128+o];
            u64 wd = pk2(w,w);
            const u64* sp2 = (const u64*)(st + kk*4);
            f01 = ffma2(wd, sp2[0], f01);
            f23 = ffma2(wd, sp2[1], f23);
        }
        if(c<7){
            float4* d = (float4*)(sw + ((c+1)&1)*8192);
            #pragma unroll
            for(int j=0;j<4;j++) d[tid + j*256] = fpre[j];
        }
        __syncthreads();
    }
    float f0,f1v,f2,f3; upk2(f01,f0,f1v); upk2(f23,f2,f3);
    if(kh==1) *(float4*)&red2[o*4] = make_float4(f0,f1v,f2,f3);
    __syncthreads();
    if(kh==0){
        float4 rv = *(const float4*)&red2[o*4];
        float fb = fc1b[o];
        float fv[4] = {f0+rv.x+fb, f1v+rv.y+fb, f2+rv.z+fb, f3+rv.w+fb};
        float fo[4];
        #pragma unroll
        for(int img=0;img<4;img++){
            int gi = (b0+img)*128 + o;
            fo[img] = lifs(fv[img], &g_sfc[gi], &g_sfv[gi]);
        }
        *(float4*)&f1_t[o*4] = make_float4(fo[0],fo[1],fo[2],fo[3]);
    }
    __syncthreads();
    if(tid < 8){
        int im = tid>>1, oo = tid&1;
        float s = 0.f;
        #pragma unroll 8
        for(int k=0;k<128;k++) s += f1_t[k*4+im]*fc2w[oo*128+k];
        dout[(b0+im)*2+oo] += s*tsw[t];
    }
}

extern "C" void kernel_launch(void* const* d_in, const int* in_sizes, int n_in,
                              void* d_out, int out_size){
    const float* x    = (const float*)d_in[0];
    const float* w1   = (const float*)d_in[1];
    const float* b1   = (const float*)d_in[2];
    const float* w2   = (const float*)d_in[3];
    const float* b2   = (const float*)d_in[4];
    const float* w3   = (const float*)d_in[5];
    const float* b3   = (const float*)d_in[6];
    const float* tcw  = (const float*)d_in[7];
    const float* tcb  = (const float*)d_in[8];
    const float* recw = (const float*)d_in[9];
    const float* recb = (const float*)d_in[10];
    const float* fc1w = (const float*)d_in[11];
    const float* fc1b = (const float*)d_in[12];
    const float* fc2w = (const float*)d_in[13];
    const float* tsw  = (const float*)d_in[14];
    float* out = (float*)d_out;

    cudaFuncSetAttribute(k_conv12, cudaFuncAttributeMaxDynamicSharedMemorySize, K2_SMEM);
    cudaFuncSetAttribute(k_conv3,  cudaFuncAttributeMaxDynamicSharedMemorySize, K3_SMEM);
    cudaFuncSetAttribute(k_tail,   cudaFuncAttributeMaxDynamicSharedMemorySize, TL_SMEM);

    k_zero<<<256,256>>>(out);
    k_prep<<<256,256>>>(w2, w3, tcw, recw, fc1w);
    for (int t=0; t<TT; t++){
        int nb = t+1 < 3 ? t+1 : 3;
        k_conv12<<<128,256,K2_SMEM>>>(x, w1, b1, b2, t);
        k_conv3<<<128,512,K3_SMEM>>>(b3, t);
        k_tail<<<64,256,TL_SMEM>>>(tcb, recb, fc1b, fc2w, tsw, out, t, nb);
    }
}

// round 11
// speedup vs baseline: 1.0509x; 1.0509x over previous
#include <cuda_runtime.h>

#define TT 32
#define BB 256
#define C1 64
#define C2 128
#define C3 256

// ---- device scratch (allocation-free) ----
__device__ float g_s1c[BB*C1*64], g_s1v[BB*C1*64];
__device__ float g_s2c[BB*C2*36], g_s2v[BB*C2*36];
__device__ float g_pool[BB*C2*9];
__device__ float g_s3c[BB*C3], g_s3v[BB*C3];
__device__ float g_flat[TT*BB*C3];
__device__ float g_stcc[BB*C3], g_stcv[BB*C3];
__device__ float g_src[BB*C3], g_srv[BB*C3];
__device__ float g_r[2*BB*C3];
__device__ float g_sfc[BB*128], g_sfv[BB*128];
__device__ float g_w2t[576*C2];
__device__ float g_w3t[1152*C3];
__device__ float g_tcwt[3*C3*C3];
__device__ float g_recwt[C3*C3];
__device__ float g_fc1wt[C3*128];

typedef unsigned long long u64;
__device__ __forceinline__ u64 pk2(float lo, float hi){
    u64 r; asm("mov.b64 %0, {%1,%2};" : "=l"(r) : "f"(lo), "f"(hi)); return r;
}
__device__ __forceinline__ void upk2(u64 v, float &lo, float &hi){
    asm("mov.b64 {%0,%1}, %2;" : "=f"(lo), "=f"(hi) : "l"(v));
}
__device__ __forceinline__ u64 ffma2(u64 a, u64 b, u64 c){
    u64 d; asm("fma.rn.f32x2 %0, %1, %2, %3;" : "=l"(d) : "l"(a), "l"(b), "l"(c)); return d;
}
// CUBA-LIF; state = (cur, veff = vlt*(1-spike))
__device__ __forceinline__ float lifs(float z, float* cp, float* vp){
    float cur = 0.5f*(*cp) + z;
    float vlt = 0.75f*(*vp) + cur;
    bool s = vlt > 0.5f;
    *cp = cur; *vp = s ? 0.0f : vlt;
    return s ? 1.0f : 0.0f;
}

__global__ void k_zero(float* __restrict__ dout){
    int i0 = blockIdx.x*blockDim.x + threadIdx.x, st = gridDim.x*blockDim.x;
    for(int i=i0;i<BB*C1*64;i+=st){ g_s1c[i]=0.f; g_s1v[i]=0.f; }
    for(int i=i0;i<BB*C2*36;i+=st){ g_s2c[i]=0.f; g_s2v[i]=0.f; }
    for(int i=i0;i<BB*C3;i+=st){
        g_s3c[i]=0.f; g_s3v[i]=0.f; g_stcc[i]=0.f; g_stcv[i]=0.f;
        g_src[i]=0.f; g_srv[i]=0.f; g_r[i]=0.f; g_r[BB*C3+i]=0.f;
    }
    for(int i=i0;i<BB*128;i+=st){ g_sfc[i]=0.f; g_sfv[i]=0.f; }
    for(int i=i0;i<BB*2;i+=st) dout[i]=0.f;
}

__global__ void k_prep(const float* __restrict__ w2, const float* __restrict__ w3,
                       const float* __restrict__ tcw, const float* __restrict__ recw,
                       const float* __restrict__ fc1w){
    int i0 = blockIdx.x*blockDim.x + threadIdx.x, st = gridDim.x*blockDim.x;
    for(int i=i0;i<C2*576;i+=st){ int co=i/576, k=i-co*576; g_w2t[k*C2+co]=w2[i]; }
    for(int i=i0;i<C3*1152;i+=st){ int co=i/1152, k=i-co*1152; g_w3t[k*C3+co]=w3[i]; }
    for(int i=i0;i<3*C3*C3;i+=st){
        int j=i/(C3*C3), r=i-j*C3*C3, o=r/C3, k=r-o*C3;
        g_tcwt[j*C3*C3 + k*C3 + o]=tcw[i];
    }
    for(int i=i0;i<C3*C3;i+=st){ int o=i/C3, k=i-o*C3; g_recwt[k*C3+o]=recw[i]; }
    for(int i=i0;i<128*C3;i+=st){ int o=i/C3, k=i-o*C3; g_fc1wt[k*128+o]=fc1w[i]; }
}

// ===== fused conv1 + conv2 + LIF + avgpool (unchanged — verified) =====
#define K2_CH    8
#define K2_CHF   (K2_CH*9*C2)
#define K2_SMEM  (8192*8 + 2*K2_CHF*4)

__global__ __launch_bounds__(256) void k_conv12(const float* __restrict__ x,
                                                const float* __restrict__ w1,
                                                const float* __restrict__ b1,
                                                const float* __restrict__ b2, int t){
    extern __shared__ char smraw[];
    u64*   sc1 = (u64*)smraw;
    float* sw  = (float*)(smraw + 8192*8);
    __shared__ float sx[200];
    int tid = threadIdx.x, b0 = blockIdx.x*2;

    if (tid < 200){
        int im = tid/100, p = tid-100*im;
        sx[tid] = x[((b0+im)*100 + p)*TT + t];
    }
    __syncthreads();
    #pragma unroll 4
    for (int l=0; l<32; l++){
        int i = l*256 + tid;
        int im = i>>12, e = i&4095;
        int c = e>>6, pos = e&63, ii = pos>>3, jj = pos&7;
        float z = __ldg(&b1[c]);
        const float* wp = w1 + c*9;
        const float* xp = sx + im*100 + ii*10 + jj;
        #pragma unroll
        for(int ki=0;ki<3;ki++)
            #pragma unroll
            for(int kj=0;kj<3;kj++)
                z += __ldg(&wp[ki*3+kj]) * xp[ki*10+kj];
        int gidx = ((b0+im)<<12) + e;
        float v = lifs(z, &g_s1c[gidx], &g_s1v[gidx]);
        sc1[i] = pk2(v,v);
    }

    int h   = tid>>7, lt = tid&127;
    int cog = lt>>2, quad = lt&3;
    int co0 = cog*4;
    int oi0 = (quad>>1)*3, oj0 = (quad&1)*3;
    const u64* scb = sc1 + h*4096;

    float4 bb = *(const float4*)&b2[co0];
    u64 acc[2][9];
    {
        u64 p0 = pk2(bb.x,bb.y), p1 = pk2(bb.z,bb.w);
        #pragma unroll
        for(int p=0;p<9;p++){ acc[0][p]=p0; acc[1][p]=p1; }
    }

    float4 pre[9];
    {
        const float4* src = (const float4*)g_w2t + tid;
        #pragma unroll
        for(int j=0;j<9;j++) pre[j] = src[j*256];
    }
    __syncthreads();
    {
        float4* dst = (float4*)sw + tid;
        #pragma unroll
        for(int j=0;j<9;j++) dst[j*256] = pre[j];
    }
    __syncthreads();

    for (int ch=0; ch<64/K2_CH; ch++){
        if (ch < 64/K2_CH - 1){
            const float4* src = (const float4*)g_w2t + (ch+1)*(K2_CHF/4) + tid;
            #pragma unroll
            for(int j=0;j<9;j++) pre[j] = src[j*256];
        }
        const float* wbuf = sw + (ch&1)*K2_CHF;
        #pragma unroll 2
        for (int cl=0; cl<K2_CH; cl++){
            int ci = ch*K2_CH + cl;
            u64 win[25];
            const u64* wr = scb + ci*64 + oi0*8 + oj0;
            #pragma unroll
            for(int di=0;di<5;di++)
                #pragma unroll
                for(int dj=0;dj<5;dj++)
                    win[di*5+dj] = wr[di*8+dj];
            #pragma unroll
            for(int kk=0;kk<9;kk++){
                const int ki = kk/3, kj = kk - ki*3;
                float4 wv = *(const float4*)&wbuf[(cl*9+kk)*C2 + co0];
                u64 w0 = pk2(wv.x,wv.y), w1p = pk2(wv.z,wv.w);
                #pragma unroll
                for(int p=0;p<9;p++){
                    const int pi = p/3, pj = p - pi*3;
                    u64 s = win[(pi+ki)*5 + (pj+kj)];
                    acc[0][p] = ffma2(w0,  s, acc[0][p]);
                    acc[1][p] = ffma2(w1p, s, acc[1][p]);
                }
            }
        }
        if (ch < 64/K2_CH - 1){
            float4* dst = (float4*)(sw + ((ch+1)&1)*K2_CHF) + tid;
            #pragma unroll
            for(int j=0;j<9;j++) dst[j*256] = pre[j];
        }
        __syncthreads();
    }

    float* zbuf = (float*)sc1;
    #pragma unroll
    for(int cp=0;cp<2;cp++)
        #pragma unroll
        for(int p=0;p<9;p++){
            float z0,z1; upk2(acc[cp][p], z0, z1);
            int di=p/3, dj=p-di*3, pidx=(oi0+di)*6 + (oj0+dj);
            zbuf[(h*C2 + co0+2*cp  )*36 + pidx] = z0;
            zbuf[(h*C2 + co0+2*cp+1)*36 + pidx] = z1;
        }
    __syncthreads();
    float* sc2 = sw;
    for(int i=tid;i<2*C2*36;i+=256){
        int gidx = b0*C2*36 + i;
        sc2[i] = lifs(zbuf[i], &g_s2c[gidx], &g_s2v[gidx]);
    }
    __syncthreads();
    for(int i=tid;i<2*C2*9;i+=256){
        int hh = i/(C2*9), rem = i - hh*(C2*9);
        int c = rem/9, pp = rem-c*9, pi = pp/3, pj = pp-pi*3;
        const float* s2 = sc2 + (hh*C2 + c)*36;
        g_pool[b0*C2*9 + i] = 0.25f*(s2[(2*pi)*6+2*pj] + s2[(2*pi)*6+2*pj+1]
                                   + s2[(2*pi+1)*6+2*pj] + s2[(2*pi+1)*6+2*pj+1]);
    }
}

// ===== conv3: K=1152 GEMV + LIF, BIG-chunk double-buffered weight staging =====
// 128 blocks = 64 img-quads x 2 co-halves. 512 threads = 128 co x 4 K-groups.
// 9 chunks of 128 K-rows; chunk buffer = 128x128 floats = 64KB (x2 buffers).
#define K3_SMEM (18432 + 2*65536 + 6144)   // sp_t | sw[2][16384] | red[3][512]
__global__ __launch_bounds__(512,1) void k_conv3(const float* __restrict__ b3, int t){
    extern __shared__ char sm3[];
    float* sp_t = (float*)sm3;                      // [1152][4]
    float* sw   = (float*)(sm3 + 18432);            // [2][128*128]
    float* red  = (float*)(sm3 + 18432 + 2*65536);  // [3][512]
    int blk = blockIdx.x, b0 = (blk>>1)*4, ch = blk&1, tid = threadIdx.x;
    for(int i=tid;i<1152;i+=512){
        float4 v;
        v.x=g_pool[(b0+0)*1152+i]; v.y=g_pool[(b0+1)*1152+i];
        v.z=g_pool[(b0+2)*1152+i]; v.w=g_pool[(b0+3)*1152+i];
        *(float4*)&sp_t[i*4]=v;
    }
    const float4* wsrc = (const float4*)g_w3t;     // row k = 64 float4; half = 32 at ch*32
    int kr0 = tid>>5, c4 = tid&31;                 // kr0 in 0..15, c4 in 0..31
    float4 pre[8];
    #pragma unroll
    for(int j=0;j<8;j++)
        pre[j] = wsrc[(kr0 + j*16)*64 + ch*32 + c4];
    {
        float4* dst = (float4*)sw;
        #pragma unroll
        for(int j=0;j<8;j++) dst[(kr0 + j*16)*32 + c4] = pre[j];
    }
    __syncthreads();
    int co_l = tid&127, kh = tid>>7;
    int co = ch*128 + co_l;
    float a0=0.f,a1=0.f,a2=0.f,a3=0.f;
    for(int c=0;c<9;c++){
        if(c<8){
            #pragma unroll
            for(int j=0;j<8;j++)
                pre[j] = wsrc[((c+1)*128 + kr0 + j*16)*64 + ch*32 + c4];
        }
        const float* wb = sw + (c&1)*16384;
        const float* st = sp_t + c*128*4;
        #pragma unroll 4
        for(int j=0;j<32;j++){
            int kk = kh*32+j;
            float w = wb[kk*128+co_l];
            float4 sv = *(const float4*)(st + kk*4);
            a0+=w*sv.x; a1+=w*sv.y; a2+=w*sv.z; a3+=w*sv.w;
        }
        if(c<8){
            float4* dst = (float4*)(sw + ((c+1)&1)*16384);
            #pragma unroll
            for(int j=0;j<8;j++) dst[(kr0 + j*16)*32 + c4] = pre[j];
        }
        __syncthreads();
    }
    if(kh>0) *(float4*)&red[(kh-1)*512 + co_l*4] = make_float4(a0,a1,a2,a3);
    __syncthreads();
    if(kh==0){
        #pragma unroll
        for(int q=0;q<3;q++){
            float4 rv = *(const float4*)&red[q*512 + co_l*4];
            a0+=rv.x; a1+=rv.y; a2+=rv.z; a3+=rv.w;
        }
        float bz = b3[co];
        float av[4] = {a0+bz, a1+bz, a2+bz, a3+bz};
        #pragma unroll
        for(int img=0;img<4;img++){
            int gi = (b0+img)*C3 + co;
            g_flat[t*BB*C3 + gi] = lifs(av[img], &g_s3c[gi], &g_s3v[gi]);
        }
    }
}

// ===== fused tail (R6 version — measured good): tc+LIF, rec+LIF, fc1+LIF, fc2 =====
// 64 blocks x 4 images, 256 threads = 256 output columns; spikes transposed [k][img].
__global__ __launch_bounds__(256) void k_tail(const float* __restrict__ tcb,
                       const float* __restrict__ recb,
                       const float* __restrict__ fc1b, const float* __restrict__ fc2w,
                       const float* __restrict__ tsw, float* __restrict__ dout,
                       int t, int nb){
    __shared__ __align__(16) float sf_t[3][1024];
    __shared__ __align__(16) float r_t[1024];
    __shared__ __align__(16) float sr_t[1024];
    __shared__ __align__(16) float f1_t[512];
    __shared__ __align__(16) float red2[512];
    int b0 = blockIdx.x*4, tid = threadIdx.x;
    for(int j=0;j<nb;j++){
        const float* fl = g_flat + (t-(nb-1)+j)*BB*C3 + b0*C3;
        #pragma unroll
        for(int img=0;img<4;img++) sf_t[j][tid*4+img] = fl[img*C3+tid];
    }
    {
        const float* rp = g_r + ((t+1)&1)*BB*C3 + b0*C3;
        #pragma unroll
        for(int img=0;img<4;img++) r_t[tid*4+img] = rp[img*C3+tid];
    }
    __syncthreads();
    int co = tid;
    // ---- temporal conv ----
    float a[4];
    {
        float bsum = 0.f;
        for(int j=0;j<nb;j++) bsum += tcb[j*C3+co];
        a[0]=a[1]=a[2]=a[3]=bsum;
    }
    for(int j=0;j<nb;j++){
        const float* w  = g_tcwt + j*C3*C3 + co;
        const float* st = sf_t[j];
        for(int k0=0;k0<C3;k0+=16){
            float wv[16];
            #pragma unroll
            for(int jj=0;jj<16;jj++) wv[jj] = w[(k0+jj)*C3];
            #pragma unroll
            for(int jj=0;jj<16;jj++){
                float4 sv = *(const float4*)(st + (k0+jj)*4);
                a[0]+=wv[jj]*sv.x; a[1]+=wv[jj]*sv.y; a[2]+=wv[jj]*sv.z; a[3]+=wv[jj]*sv.w;
            }
        }
    }
    float tcs[4];
    #pragma unroll
    for(int img=0;img<4;img++){
        int gi = (b0+img)*C3 + co;
        tcs[img] = lifs(a[img], &g_stcc[gi], &g_stcv[gi]);
    }
    // ---- recurrent ----
    {
        float rb = recb[co];
        #pragma unroll
        for(int img=0;img<4;img++) a[img] = tcs[img] + rb;
        const float* w = g_recwt + co;
        for(int k0=0;k0<C3;k0+=16){
            float wv[16];
            #pragma unroll
            for(int jj=0;jj<16;jj++) wv[jj] = w[(k0+jj)*C3];
            #pragma unroll
            for(int jj=0;jj<16;jj++){
                float4 sv = *(const float4*)(r_t + (k0+jj)*4);
                a[0]+=wv[jj]*sv.x; a[1]+=wv[jj]*sv.y; a[2]+=wv[jj]*sv.z; a[3]+=wv[jj]*sv.w;
            }
        }
    }
    {
        float rs[4];
        #pragma unroll
        for(int img=0;img<4;img++){
            int gi = (b0+img)*C3 + co;
            rs[img] = lifs(a[img], &g_src[gi], &g_srv[gi]);
            g_r[(t&1)*BB*C3 + gi] = rs[img];
        }
        *(float4*)&sr_t[co*4] = make_float4(rs[0],rs[1],rs[2],rs[3]);
    }
    __syncthreads();
    // ---- fc1 (128 out, K split in halves across tid>>7) ----
    int o = tid&127, kh = tid>>7;
    float f[4]={0.f,0.f,0.f,0.f};
    {
        const float* w  = g_fc1wt + (kh*128)*128 + o;
        const float* st = sr_t + kh*128*4;
        for(int k0=0;k0<128;k0+=16){
            float wv[16];
            #pragma unroll
            for(int jj=0;jj<16;jj++) wv[jj] = w[(k0+jj)*128];
            #pragma unroll
            for(int jj=0;jj<16;jj++){
                float4 sv = *(const float4*)(st + (k0+jj)*4);
                f[0]+=wv[jj]*sv.x; f[1]+=wv[jj]*sv.y; f[2]+=wv[jj]*sv.z; f[3]+=wv[jj]*sv.w;
            }
        }
    }
    if (kh==1) *(float4*)&red2[o*4] = make_float4(f[0],f[1],f[2],f[3]);
    __syncthreads();
    if (kh==0){
        float4 rv = *(const float4*)&red2[o*4];
        float fb = fc1b[o];
        float fv[4] = {f[0]+rv.x+fb, f[1]+rv.y+fb, f[2]+rv.z+fb, f[3]+rv.w+fb};
        float fo[4];
        #pragma unroll
        for(int img=0;img<4;img++){
            int gi = (b0+img)*128 + o;
            fo[img] = lifs(fv[img], &g_sfc[gi], &g_sfv[gi]);
        }
        *(float4*)&f1_t[o*4] = make_float4(fo[0],fo[1],fo[2],fo[3]);
    }
    __syncthreads();
    // ---- fc2 accumulate ----
    if (tid < 8){
        int im = tid>>1, oo = tid&1;
        float s = 0.f;
        #pragma unroll 8
        for(int k=0;k<128;k++) s += f1_t[k*4+im]*fc2w[oo*128+k];
        dout[(b0+im)*2+oo] += s*tsw[t];
    }
}

extern "C" void kernel_launch(void* const* d_in, const int* in_sizes, int n_in,
                              void* d_out, int out_size){
    const float* x    = (const float*)d_in[0];
    const float* w1   = (const float*)d_in[1];
    const float* b1   = (const float*)d_in[2];
    const float* w2   = (const float*)d_in[3];
    const float* b2   = (const float*)d_in[4];
    const float* w3   = (const float*)d_in[5];
    const float* b3   = (const float*)d_in[6];
    const float* tcw  = (const float*)d_in[7];
    const float* tcb  = (const float*)d_in[8];
    const float* recw = (const float*)d_in[9];
    const float* recb = (const float*)d_in[10];
    const float* fc1w = (const float*)d_in[11];
    const float* fc1b = (const float*)d_in[12];
    const float* fc2w = (const float*)d_in[13];
    const float* tsw  = (const float*)d_in[14];
    float* out = (float*)d_out;

    cudaFuncSetAttribute(k_conv12, cudaFuncAttributeMaxDynamicSharedMemorySize, K2_SMEM);
    cudaFuncSetAttribute(k_conv3,  cudaFuncAttributeMaxDynamicSharedMemorySize, K3_SMEM);

    k_zero<<<256,256>>>(out);
    k_prep<<<256,256>>>(w2, w3, tcw, recw, fc1w);
    for (int t=0; t<TT; t++){
        int nb = t+1 < 3 ? t+1 : 3;
        k_conv12<<<128,256,K2_SMEM>>>(x, w1, b1, b2, t);
        k_conv3<<<128,512,K3_SMEM>>>(b3, t);
        k_tail<<<64,256>>>(tcb, recb, fc1b, fc2w, tsw, out, t, nb);
    }
}

// round 13
// speedup vs baseline: 1.4109x; 1.3425x over previous
#include <cuda_runtime.h>

#define TT 32
#define BB 256
#define C1 64
#define C2 128
#define C3 256

// ---- device scratch (allocation-free) ----
__device__ float g_s1c[BB*C1*64], g_s1v[BB*C1*64];
__device__ float g_s2c[BB*C2*36], g_s2v[BB*C2*36];
__device__ float g_pool[2*BB*C2*9];          // double-buffered by t&1 (pipelined)
__device__ float g_s3c[BB*C3], g_s3v[BB*C3];
__device__ float g_flat[TT*BB*C3];
__device__ float g_stcc[BB*C3], g_stcv[BB*C3];
__device__ float g_src[BB*C3], g_srv[BB*C3];
__device__ float g_r[2*BB*C3];
__device__ float g_sfc[BB*128], g_sfv[BB*128];
__device__ float g_w2t[576*C2];
__device__ float g_w3t[1152*C3];
__device__ float g_tcwt[3*C3*C3];
__device__ float g_recwt[C3*C3];
__device__ float g_fc1wt[C3*128];

typedef unsigned long long u64;
__device__ __forceinline__ u64 pk2(float lo, float hi){
    u64 r; asm("mov.b64 %0, {%1,%2};" : "=l"(r) : "f"(lo), "f"(hi)); return r;
}
__device__ __forceinline__ void upk2(u64 v, float &lo, float &hi){
    asm("mov.b64 {%0,%1}, %2;" : "=f"(lo), "=f"(hi) : "l"(v));
}
__device__ __forceinline__ u64 ffma2(u64 a, u64 b, u64 c){
    u64 d; asm("fma.rn.f32x2 %0, %1, %2, %3;" : "=l"(d) : "l"(a), "l"(b), "l"(c)); return d;
}
// CUBA-LIF; state = (cur, veff = vlt*(1-spike))
__device__ __forceinline__ float lifs(float z, float* cp, float* vp){
    float cur = 0.5f*(*cp) + z;
    float vlt = 0.75f*(*vp) + cur;
    bool s = vlt > 0.5f;
    *cp = cur; *vp = s ? 0.0f : vlt;
    return s ? 1.0f : 0.0f;
}

__global__ void k_zero(float* __restrict__ dout){
    int i0 = blockIdx.x*blockDim.x + threadIdx.x, st = gridDim.x*blockDim.x;
    for(int i=i0;i<BB*C1*64;i+=st){ g_s1c[i]=0.f; g_s1v[i]=0.f; }
    for(int i=i0;i<BB*C2*36;i+=st){ g_s2c[i]=0.f; g_s2v[i]=0.f; }
    for(int i=i0;i<BB*C3;i+=st){
        g_s3c[i]=0.f; g_s3v[i]=0.f; g_stcc[i]=0.f; g_stcv[i]=0.f;
        g_src[i]=0.f; g_srv[i]=0.f; g_r[i]=0.f; g_r[BB*C3+i]=0.f;
    }
    for(int i=i0;i<BB*128;i+=st){ g_sfc[i]=0.f; g_sfv[i]=0.f; }
    for(int i=i0;i<BB*2;i+=st) dout[i]=0.f;
}

__global__ void k_prep(const float* __restrict__ w2, const float* __restrict__ w3,
                       const float* __restrict__ tcw, const float* __restrict__ recw,
                       const float* __restrict__ fc1w){
    int i0 = blockIdx.x*blockDim.x + threadIdx.x, st = gridDim.x*blockDim.x;
    for(int i=i0;i<C2*576;i+=st){ int co=i/576, k=i-co*576; g_w2t[k*C2+co]=w2[i]; }
    for(int i=i0;i<C3*1152;i+=st){ int co=i/1152, k=i-co*1152; g_w3t[k*C3+co]=w3[i]; }
    for(int i=i0;i<3*C3*C3;i+=st){
        int j=i/(C3*C3), r=i-j*C3*C3, o=r/C3, k=r-o*C3;
        g_tcwt[j*C3*C3 + k*C3 + o]=tcw[i];
    }
    for(int i=i0;i<C3*C3;i+=st){ int o=i/C3, k=i-o*C3; g_recwt[k*C3+o]=recw[i]; }
    for(int i=i0;i<128*C3;i+=st){ int o=i/C3, k=i-o*C3; g_fc1wt[k*128+o]=fc1w[i]; }
}

// ===== fused conv1 + conv2 + LIF + avgpool (unchanged — verified) =====
#define K2_CH    8
#define K2_CHF   (K2_CH*9*C2)
#define K2_SMEM  (8192*8 + 2*K2_CHF*4)

__global__ __launch_bounds__(256) void k_conv12(const float* __restrict__ x,
                                                const float* __restrict__ w1,
                                                const float* __restrict__ b1,
                                                const float* __restrict__ b2, int t){
    extern __shared__ char smraw[];
    u64*   sc1 = (u64*)smraw;
    float* sw  = (float*)(smraw + 8192*8);
    __shared__ float sx[200];
    int tid = threadIdx.x, b0 = blockIdx.x*2;

    if (tid < 200){
        int im = tid/100, p = tid-100*im;
        sx[tid] = x[((b0+im)*100 + p)*TT + t];
    }
    __syncthreads();
    #pragma unroll 4
    for (int l=0; l<32; l++){
        int i = l*256 + tid;
        int im = i>>12, e = i&4095;
        int c = e>>6, pos = e&63, ii = pos>>3, jj = pos&7;
        float z = __ldg(&b1[c]);
        const float* wp = w1 + c*9;
        const float* xp = sx + im*100 + ii*10 + jj;
        #pragma unroll
        for(int ki=0;ki<3;ki++)
            #pragma unroll
            for(int kj=0;kj<3;kj++)
                z += __ldg(&wp[ki*3+kj]) * xp[ki*10+kj];
        int gidx = ((b0+im)<<12) + e;
        float v = lifs(z, &g_s1c[gidx], &g_s1v[gidx]);
        sc1[i] = pk2(v,v);
    }

    int h   = tid>>7, lt = tid&127;
    int cog = lt>>2, quad = lt&3;
    int co0 = cog*4;
    int oi0 = (quad>>1)*3, oj0 = (quad&1)*3;
    const u64* scb = sc1 + h*4096;

    float4 bb = *(const float4*)&b2[co0];
    u64 acc[2][9];
    {
        u64 p0 = pk2(bb.x,bb.y), p1 = pk2(bb.z,bb.w);
        #pragma unroll
        for(int p=0;p<9;p++){ acc[0][p]=p0; acc[1][p]=p1; }
    }

    float4 pre[9];
    {
        const float4* src = (const float4*)g_w2t + tid;
        #pragma unroll
        for(int j=0;j<9;j++) pre[j] = src[j*256];
    }
    __syncthreads();
    {
        float4* dst = (float4*)sw + tid;
        #pragma unroll
        for(int j=0;j<9;j++) dst[j*256] = pre[j];
    }
    __syncthreads();

    for (int ch=0; ch<64/K2_CH; ch++){
        if (ch < 64/K2_CH - 1){
            const float4* src = (const float4*)g_w2t + (ch+1)*(K2_CHF/4) + tid;
            #pragma unroll
            for(int j=0;j<9;j++) pre[j] = src[j*256];
        }
        const float* wbuf = sw + (ch&1)*K2_CHF;
        #pragma unroll 2
        for (int cl=0; cl<K2_CH; cl++){
            int ci = ch*K2_CH + cl;
            u64 win[25];
            const u64* wr = scb + ci*64 + oi0*8 + oj0;
            #pragma unroll
            for(int di=0;di<5;di++)
                #pragma unroll
                for(int dj=0;dj<5;dj++)
                    win[di*5+dj] = wr[di*8+dj];
            #pragma unroll
            for(int kk=0;kk<9;kk++){
                const int ki = kk/3, kj = kk - ki*3;
                float4 wv = *(const float4*)&wbuf[(cl*9+kk)*C2 + co0];
                u64 w0 = pk2(wv.x,wv.y), w1p = pk2(wv.z,wv.w);
                #pragma unroll
                for(int p=0;p<9;p++){
                    const int pi = p/3, pj = p - pi*3;
                    u64 s = win[(pi+ki)*5 + (pj+kj)];
                    acc[0][p] = ffma2(w0,  s, acc[0][p]);
                    acc[1][p] = ffma2(w1p, s, acc[1][p]);
                }
            }
        }
        if (ch < 64/K2_CH - 1){
            float4* dst = (float4*)(sw + ((ch+1)&1)*K2_CHF) + tid;
            #pragma unroll
            for(int j=0;j<9;j++) dst[j*256] = pre[j];
        }
        __syncthreads();
    }

    float* zbuf = (float*)sc1;
    #pragma unroll
    for(int cp=0;cp<2;cp++)
        #pragma unroll
        for(int p=0;p<9;p++){
            float z0,z1; upk2(acc[cp][p], z0, z1);
            int di=p/3, dj=p-di*3, pidx=(oi0+di)*6 + (oj0+dj);
            zbuf[(h*C2 + co0+2*cp  )*36 + pidx] = z0;
            zbuf[(h*C2 + co0+2*cp+1)*36 + pidx] = z1;
        }
    __syncthreads();
    float* sc2 = sw;
    for(int i=tid;i<2*C2*36;i+=256){
        int gidx = b0*C2*36 + i;
        sc2[i] = lifs(zbuf[i], &g_s2c[gidx], &g_s2v[gidx]);
    }
    __syncthreads();
    float* pout = g_pool + (t&1)*BB*C2*9;
    for(int i=tid;i<2*C2*9;i+=256){
        int hh = i/(C2*9), rem = i - hh*(C2*9);
        int c = rem/9, pp = rem-c*9, pi = pp/3, pj = pp-pi*3;
        const float* s2 = sc2 + (hh*C2 + c)*36;
        pout[b0*C2*9 + i] = 0.25f*(s2[(2*pi)*6+2*pj] + s2[(2*pi)*6+2*pj+1]
                                 + s2[(2*pi+1)*6+2*pj] + s2[(2*pi+1)*6+2*pj+1]);
    }
}

// ===== conv3: K=1152 GEMV + LIF, big-chunk double-buffered weight staging =====
#define K3_SMEM (18432 + 2*65536 + 6144)   // sp_t | sw[2][16384] | red[3][512]
__global__ __launch_bounds__(512,1) void k_conv3(const float* __restrict__ b3, int t){
    extern __shared__ char sm3[];
    float* sp_t = (float*)sm3;                      // [1152][4]
    float* sw   = (float*)(sm3 + 18432);            // [2][128*128]
    float* red  = (float*)(sm3 + 18432 + 2*65536);  // [3][512]
    int blk = blockIdx.x, b0 = (blk>>1)*4, ch = blk&1, tid = threadIdx.x;
    const float* pin = g_pool + (t&1)*BB*C2*9;
    for(int i=tid;i<1152;i+=512){
        float4 v;
        v.x=pin[(b0+0)*1152+i]; v.y=pin[(b0+1)*1152+i];
        v.z=pin[(b0+2)*1152+i]; v.w=pin[(b0+3)*1152+i];
        *(float4*)&sp_t[i*4]=v;
    }
    const float4* wsrc = (const float4*)g_w3t;
    int kr0 = tid>>5, c4 = tid&31;
    float4 pre[8];
    #pragma unroll
    for(int j=0;j<8;j++)
        pre[j] = wsrc[(kr0 + j*16)*64 + ch*32 + c4];
    {
        float4* dst = (float4*)sw;
        #pragma unroll
        for(int j=0;j<8;j++) dst[(kr0 + j*16)*32 + c4] = pre[j];
    }
    __syncthreads();
    int co_l = tid&127, kh = tid>>7;
    int co = ch*128 + co_l;
    float a0=0.f,a1=0.f,a2=0.f,a3=0.f;
    for(int c=0;c<9;c++){
        if(c<8){
            #pragma unroll
            for(int j=0;j<8;j++)
                pre[j] = wsrc[((c+1)*128 + kr0 + j*16)*64 + ch*32 + c4];
        }
        const float* wb = sw + (c&1)*16384;
        const float* st = sp_t + c*128*4;
        #pragma unroll 4
        for(int j=0;j<32;j++){
            int kk = kh*32+j;
            float w = wb[kk*128+co_l];
            float4 sv = *(const float4*)(st + kk*4);
            a0+=w*sv.x; a1+=w*sv.y; a2+=w*sv.z; a3+=w*sv.w;
        }
        if(c<8){
            float4* dst = (float4*)(sw + ((c+1)&1)*16384);
            #pragma unroll
            for(int j=0;j<8;j++) dst[(kr0 + j*16)*32 + c4] = pre[j];
        }
        __syncthreads();
    }
    if(kh>0) *(float4*)&red[(kh-1)*512 + co_l*4] = make_float4(a0,a1,a2,a3);
    __syncthreads();
    if(kh==0){
        #pragma unroll
        for(int q=0;q<3;q++){
            float4 rv = *(const float4*)&red[q*512 + co_l*4];
            a0+=rv.x; a1+=rv.y; a2+=rv.z; a3+=rv.w;
        }
        float bz = b3[co];
        float av[4] = {a0+bz, a1+bz, a2+bz, a3+bz};
        #pragma unroll
        for(int img=0;img<4;img++){
            int gi = (b0+img)*C3 + co;
            g_flat[t*BB*C3 + gi] = lifs(av[img], &g_s3c[gi], &g_s3v[gi]);
        }
    }
}

// ===== fused tail (R6 version — measured good) =====
__global__ __launch_bounds__(256) void k_tail(const float* __restrict__ tcb,
                       const float* __restrict__ recb,
                       const float* __restrict__ fc1b, const float* __restrict__ fc2w,
                       const float* __restrict__ tsw, float* __restrict__ dout,
                       int t, int nb){
    __shared__ __align__(16) float sf_t[3][1024];
    __shared__ __align__(16) float r_t[1024];
    __shared__ __align__(16) float sr_t[1024];
    __shared__ __align__(16) float f1_t[512];
    __shared__ __align__(16) float red2[512];
    int b0 = blockIdx.x*4, tid = threadIdx.x;
    for(int j=0;j<nb;j++){
        const float* fl = g_flat + (t-(nb-1)+j)*BB*C3 + b0*C3;
        #pragma unroll
        for(int img=0;img<4;img++) sf_t[j][tid*4+img] = fl[img*C3+tid];
    }
    {
        const float* rp = g_r + ((t+1)&1)*BB*C3 + b0*C3;
        #pragma unroll
        for(int img=0;img<4;img++) r_t[tid*4+img] = rp[img*C3+tid];
    }
    __syncthreads();
    int co = tid;
    float a[4];
    {
        float bsum = 0.f;
        for(int j=0;j<nb;j++) bsum += tcb[j*C3+co];
        a[0]=a[1]=a[2]=a[3]=bsum;
    }
    for(int j=0;j<nb;j++){
        const float* w  = g_tcwt + j*C3*C3 + co;
        const float* st = sf_t[j];
        for(int k0=0;k0<C3;k0+=16){
            float wv[16];
            #pragma unroll
            for(int jj=0;jj<16;jj++) wv[jj] = w[(k0+jj)*C3];
            #pragma unroll
            for(int jj=0;jj<16;jj++){
                float4 sv = *(const float4*)(st + (k0+jj)*4);
                a[0]+=wv[jj]*sv.x; a[1]+=wv[jj]*sv.y; a[2]+=wv[jj]*sv.z; a[3]+=wv[jj]*sv.w;
            }
        }
    }
    float tcs[4];
    #pragma unroll
    for(int img=0;img<4;img++){
        int gi = (b0+img)*C3 + co;
        tcs[img] = lifs(a[img], &g_stcc[gi], &g_stcv[gi]);
    }
    {
        float rb = recb[co];
        #pragma unroll
        for(int img=0;img<4;img++) a[img] = tcs[img] + rb;
        const float* w = g_recwt + co;
        for(int k0=0;k0<C3;k0+=16){
            float wv[16];
            #pragma unroll
            for(int jj=0;jj<16;jj++) wv[jj] = w[(k0+jj)*C3];
            #pragma unroll
            for(int jj=0;jj<16;jj++){
                float4 sv = *(const float4*)(r_t + (k0+jj)*4);
                a[0]+=wv[jj]*sv.x; a[1]+=wv[jj]*sv.y; a[2]+=wv[jj]*sv.z; a[3]+=wv[jj]*sv.w;
            }
        }
    }
    {
        float rs[4];
        #pragma unroll
        for(int img=0;img<4;img++){
            int gi = (b0+img)*C3 + co;
            rs[img] = lifs(a[img], &g_src[gi], &g_srv[gi]);
            g_r[(t&1)*BB*C3 + gi] = rs[img];
        }
        *(float4*)&sr_t[co*4] = make_float4(rs[0],rs[1],rs[2],rs[3]);
    }
    __syncthreads();
    int o = tid&127, kh = tid>>7;
    float f[4]={0.f,0.f,0.f,0.f};
    {
        const float* w  = g_fc1wt + (kh*128)*128 + o;
        const float* st = sr_t + kh*128*4;
        for(int k0=0;k0<128;k0+=16){
            float wv[16];
            #pragma unroll
            for(int jj=0;jj<16;jj++) wv[jj] = w[(k0+jj)*128];
            #pragma unroll
            for(int jj=0;jj<16;jj++){
                float4 sv = *(const float4*)(st + (k0+jj)*4);
                f[0]+=wv[jj]*sv.x; f[1]+=wv[jj]*sv.y; f[2]+=wv[jj]*sv.z; f[3]+=wv[jj]*sv.w;
            }
        }
    }
    if (kh==1) *(float4*)&red2[o*4] = make_float4(f[0],f[1],f[2],f[3]);
    __syncthreads();
    if (kh==0){
        float4 rv = *(const float4*)&red2[o*4];
        float fb = fc1b[o];
        float fv[4] = {f[0]+rv.x+fb, f[1]+rv.y+fb, f[2]+rv.z+fb, f[3]+rv.w+fb};
        float fo[4];
        #pragma unroll
        for(int img=0;img<4;img++){
            int gi = (b0+img)*128 + o;
            fo[img] = lifs(fv[img], &g_sfc[gi], &g_sfv[gi]);
        }
        *(float4*)&f1_t[o*4] = make_float4(fo[0],fo[1],fo[2],fo[3]);
    }
    __syncthreads();
    if (tid < 8){
        int im = tid>>1, oo = tid&1;
        float s = 0.f;
        #pragma unroll 8
        for(int k=0;k<128;k++) s += f1_t[k*4+im]*fc2w[oo*128+k];
        dout[(b0+im)*2+oo] += s*tsw[t];
    }
}

extern "C" void kernel_launch(void* const* d_in, const int* in_sizes, int n_in,
                              void* d_out, int out_size){
    const float* x    = (const float*)d_in[0];
    const float* w1   = (const float*)d_in[1];
    const float* b1   = (const float*)d_in[2];
    const float* w2   = (const float*)d_in[3];
    const float* b2   = (const float*)d_in[4];
    const float* w3   = (const float*)d_in[5];
    const float* b3   = (const float*)d_in[6];
    const float* tcw  = (const float*)d_in[7];
    const float* tcb  = (const float*)d_in[8];
    const float* recw = (const float*)d_in[9];
    const float* recb = (const float*)d_in[10];
    const float* fc1w = (const float*)d_in[11];
    const float* fc1b = (const float*)d_in[12];
    const float* fc2w = (const float*)d_in[13];
    const float* tsw  = (const float*)d_in[14];
    float* out = (float*)d_out;

    // One-time host-side setup: extra streams + events for 3-stage time pipelining.
    static cudaStream_t s2 = nullptr, s3 = nullptr;
    static cudaEvent_t evI, evJ2, evJ3, ev12[4], evC3[4];
    if (!s2){
        cudaStreamCreateWithFlags(&s2, cudaStreamNonBlocking);
        cudaStreamCreateWithFlags(&s3, cudaStreamNonBlocking);
        cudaEventCreateWithFlags(&evI,  cudaEventDisableTiming);
        cudaEventCreateWithFlags(&evJ2, cudaEventDisableTiming);
        cudaEventCreateWithFlags(&evJ3, cudaEventDisableTiming);
        for(int i=0;i<4;i++){
            cudaEventCreateWithFlags(&ev12[i], cudaEventDisableTiming);
            cudaEventCreateWithFlags(&evC3[i], cudaEventDisableTiming);
        }
        cudaFuncSetAttribute(k_conv12, cudaFuncAttributeMaxDynamicSharedMemorySize, K2_SMEM);
        cudaFuncSetAttribute(k_conv3,  cudaFuncAttributeMaxDynamicSharedMemorySize, K3_SMEM);
    }

    k_zero<<<256,256>>>(out);
    k_prep<<<256,256>>>(w2, w3, tcw, recw, fc1w);
    cudaEventRecord(evI, 0);
    cudaStreamWaitEvent(s2, evI, 0);
    cudaStreamWaitEvent(s3, evI, 0);

    for (int t=0; t<TT; t++){
        int nb = t+1 < 3 ? t+1 : 3;
        // pool[t&1] reuse guard: conv12(t) must not overwrite before conv3(t-2) read it
        if (t >= 2) cudaStreamWaitEvent(0, evC3[(t-2)&3], 0);
        k_conv12<<<128,256,K2_SMEM,0>>>(x, w1, b1, b2, t);
        cudaEventRecord(ev12[t&3], 0);

        cudaStreamWaitEvent(s2, ev12[t&3], 0);
        k_conv3<<<128,512,K3_SMEM,s2>>>(b3, t);
        cudaEventRecord(evC3[t&3], s2);

        cudaStreamWaitEvent(s3, evC3[t&3], 0);
        k_tail<<<64,256,0,s3>>>(tcb, recb, fc1b, fc2w, tsw, out, t, nb);
    }

    // join forked streams back into the capture/origin stream
    cudaEventRecord(evJ2, s2);
    cudaEventRecord(evJ3, s3);
    cudaStreamWaitEvent(0, evJ2, 0);
    cudaStreamWaitEvent(0, evJ3, 0);
}